// round 10
// baseline (speedup 1.0000x reference)
#include <cuda_runtime.h>
#include <cuda_fp16.h>
#include <math.h>

#define N_RAYS (4*128*128)
#define WARPS_PER_BLOCK 8

// padded z-pair packed volume: P2(b, xp, yp, zp) = half2( vpad(x,y,z), vpad(x,y,z+1) )
// xp = x+1 (x in [-1,129]), yp = y+1 (y in [-1,128]), zp = z+4 (z in [-4,131])
#define PZ 136
#define PY 130
#define PX 131
#define SX (PY*PZ)             // 17680
#define PBATCH (PX*SX)         // 2316080
#define ROFF (SX + PZ + 4)     // 17820

__device__ float4   g_ray[N_RAYS * 2];
__device__ unsigned g_P2[4 * PBATCH];      // 37 MB

// ---------------- setup: per-ray geometry ----------------
__global__ void __launch_bounds__(128) drr_setup_kernel(
    const float* __restrict__ params)   // (4,6)
{
    const int ray = blockIdx.x * 128 + threadIdx.x;
    const int iv = ray & 127;
    const int iu = (ray >> 7) & 127;
    const int b  = ray >> 14;

    const float* p = params + b * 6;
    float sx, cx, sy, cy, sz, cz;
    __sincosf(p[0], &sx, &cx);
    __sincosf(p[1], &sy, &cy);
    __sincosf(p[2], &sz, &cz);

    float T00 = cy*cz,  T01 = cx*sz + sx*sy*cz,  T02 = sx*sz - cx*sy*cz;
    float T10 = -cy*sz, T11 = cx*cz - sx*sy*sz,  T12 = sx*cz + cx*sy*sz;
    float T20 = sy,     T21 = -sx*cy,            T22 = cx*cy;

    float tv0 = -p[3], tv1 = -p[4], tv2 = 1000.0f - p[5];
    float s0 = 64.0f - (T00*tv0 + T01*tv1 + T02*tv2);
    float s1 = 64.0f - (T10*tv0 + T11*tv1 + T12*tv2);
    float s2 = 64.0f - (T20*tv0 + T21*tv1 + T22*tv2);

    float qx = ((float)iu + 0.5f) * 0.001f - 0.064f;
    float qy = ((float)iv + 0.5f) * 0.001f - 0.064f;

    float d0 = T00*qx + T01*qy + T02;
    float d1 = T10*qx + T11*qy + T12;
    float d2 = T20*qx + T21*qy + T22;
    float nrm = sqrtf(d0*d0 + d1*d1 + d2*d2);
    d0 /= nrm; d1 /= nrm; d2 /= nrm;

    float sd0 = (fabsf(d0) < 1e-8f) ? 1e-8f : d0;
    float sd1 = (fabsf(d1) < 1e-8f) ? 1e-8f : d1;
    float sd2 = (fabsf(d2) < 1e-8f) ? 1e-8f : d2;
    float a0 = (0.0f - s0) / sd0, b0_ = (128.0f - s0) / sd0;
    float a1 = (0.0f - s1) / sd1, b1_ = (128.0f - s1) / sd1;
    float a2 = (0.0f - s2) / sd2, b2_ = (128.0f - s2) / sd2;
    float tmin = fmaxf(fmaxf(fminf(a0,b0_), fminf(a1,b1_)), fminf(a2,b2_));
    tmin = fmaxf(tmin, 0.0f);
    float tmax = fminf(fminf(fmaxf(a0,b0_), fmaxf(a1,b1_)), fmaxf(a2,b2_));

    g_ray[ray*2 + 0] = make_float4(s0, s1, s2, tmin);
    g_ray[ray*2 + 1] = make_float4(d0, d1, d2, tmax);
}

// ---------------- pack: z-pair rows (reads each vol row ONCE) ----------------
__global__ void __launch_bounds__(256) drr_pack_kernel(
    const float* __restrict__ vol)
{
    const int tid = blockIdx.x * 256 + threadIdx.x;   // 4*128*128*16
    const int zb = tid & 15;
    const int y  = (tid >> 4) & 127;
    const int x  = (tid >> 11) & 127;
    const int b  = tid >> 18;

    const size_t row = (((size_t)(b * 128 + x)) * 128 + y) * 128;
    const int z0 = zb * 8;

    float4 a0 = __ldg((const float4*)(vol + row + z0));
    float4 a1 = __ldg((const float4*)(vol + row + z0 + 4));
    float nxt = (zb < 15) ? __ldg(vol + row + z0 + 8) : 0.0f;  // v(z0+8); z=128 pad -> 0

    __half2 h0 = __floats2half2_rn(a0.x, a0.y);
    __half2 h1 = __floats2half2_rn(a0.y, a0.z);
    __half2 h2 = __floats2half2_rn(a0.z, a0.w);
    __half2 h3 = __floats2half2_rn(a0.w, a1.x);
    __half2 h4 = __floats2half2_rn(a1.x, a1.y);
    __half2 h5 = __floats2half2_rn(a1.y, a1.z);
    __half2 h6 = __floats2half2_rn(a1.z, a1.w);
    __half2 h7 = __floats2half2_rn(a1.w, nxt);

    uint4 o0, o1;
    o0.x = *reinterpret_cast<unsigned*>(&h0);
    o0.y = *reinterpret_cast<unsigned*>(&h1);
    o0.z = *reinterpret_cast<unsigned*>(&h2);
    o0.w = *reinterpret_cast<unsigned*>(&h3);
    o1.x = *reinterpret_cast<unsigned*>(&h4);
    o1.y = *reinterpret_cast<unsigned*>(&h5);
    o1.z = *reinterpret_cast<unsigned*>(&h6);
    o1.w = *reinterpret_cast<unsigned*>(&h7);

    size_t base = (size_t)b * PBATCH + (size_t)(x + 1) * SX + (size_t)(y + 1) * PZ;
    *reinterpret_cast<uint4*>(&g_P2[base + z0 + 4]) = o0;
    *reinterpret_cast<uint4*>(&g_P2[base + z0 + 8]) = o1;

    if (zb == 0) {
        // slot z=-1 (zp=3): (v(-1)=0, v(0))
        __half2 hl = __floats2half2_rn(0.0f, a0.x);
        g_P2[base + 3] = *reinterpret_cast<unsigned*>(&hl);
    }
}

// ---------------- borders: zero planes + z-pads ----------------
__global__ void __launch_bounds__(256) drr_border_kernel()
{
    const int t = blockIdx.x * 256 + threadIdx.x;     // 4*PX*PY
    if (t >= 4 * PX * PY) return;
    const int yp = t % PY;
    const int r2 = t / PY;
    const int xp = r2 % PX;
    const int b  = r2 / PX;

    size_t base = (size_t)b * PBATCH + (size_t)xp * SX + (size_t)yp * PZ;
    uint4 z4 = make_uint4(0u, 0u, 0u, 0u);

    if (xp == 0 || xp == 129 || xp == 130 || yp == 0 || yp == 129) {
        #pragma unroll
        for (int i = 0; i < PZ / 4; i++)
            *reinterpret_cast<uint4*>(&g_P2[base + i * 4]) = z4;
    } else {
        *reinterpret_cast<uint4*>(&g_P2[base])       = z4;   // zp 0..3 (zp=3 overwritten by pack)
        *reinterpret_cast<uint4*>(&g_P2[base + 132]) = z4;   // zp 132..135
    }
}

// ---------------- march ----------------
__device__ __forceinline__ float drr_lerp(
    const unsigned* __restrict__ P,
    float px, float py, float pz)
{
    float fx = floorf(px), fy = floorf(py), fz = floorf(pz);
    float rx = px - fx, ry = py - fy, rz = pz - fz;

    int r = (int)fmaf(fx, (float)SX, fmaf(fy, (float)PZ, fz + (float)ROFF));

    unsigned u00 = __ldg(P + r);            // (x,   y)   -> (v(z), v(z+1))
    unsigned u01 = __ldg(P + r + PZ);       // (x,   y+1)
    unsigned u10 = __ldg(P + r + SX);       // (x+1, y)
    unsigned u11 = __ldg(P + r + SX + PZ);  // (x+1, y+1)

    float2 f00 = __half22float2(*reinterpret_cast<__half2*>(&u00));
    float2 f01 = __half22float2(*reinterpret_cast<__half2*>(&u01));
    float2 f10 = __half22float2(*reinterpret_cast<__half2*>(&u10));
    float2 f11 = __half22float2(*reinterpret_cast<__half2*>(&u11));

    float za = fmaf(rz, f00.y - f00.x, f00.x);
    float zb = fmaf(rz, f01.y - f01.x, f01.x);
    float zc = fmaf(rz, f10.y - f10.x, f10.x);
    float zd = fmaf(rz, f11.y - f11.x, f11.x);
    float ly0 = fmaf(ry, zb - za, za);
    float ly1 = fmaf(ry, zd - zc, zc);
    return fmaf(rx, ly1 - ly0, ly0);
}

// unmasked sample: only valid when every lane in the chunk has tk < tmax
__device__ __forceinline__ float drr_sample_u(
    const unsigned* __restrict__ P, float tk,
    float d0, float d1, float d2, float s0, float s1, float s2)
{
    return drr_lerp(P, fmaf(tk, d0, s0), fmaf(tk, d1, s1), fmaf(tk, d2, s2));
}

// masked sample (final chunk)
__device__ __forceinline__ float drr_sample_m(
    const unsigned* __restrict__ P, float tk, float tmax,
    float d0, float d1, float d2, float s0, float s1, float s2)
{
    float tc = fminf(tk, tmax);
    float s = drr_lerp(P, fmaf(tc, d0, s0), fmaf(tc, d1, s1), fmaf(tc, d2, s2));
    return (tk < tmax) ? s : 0.0f;
}

__global__ void __launch_bounds__(WARPS_PER_BLOCK * 32, 6) drr_march_kernel(
    float* __restrict__ out)
{
    const int lane    = threadIdx.x & 31;
    const int warp_id = threadIdx.x >> 5;
    const int ray     = blockIdx.x * WARPS_PER_BLOCK + warp_id;
    const int b       = ray >> 14;

    const float4 A = __ldg(&g_ray[ray*2 + 0]);
    const float4 B = __ldg(&g_ray[ray*2 + 1]);
    const float s0 = A.x, s1 = A.y, s2 = A.z, tmin = A.w;
    const float d0 = B.x, d1 = B.y, d2 = B.z, tmax = B.w;

    const unsigned* __restrict__ P = g_P2 + (size_t)b * PBATCH;

    int nc = __float2int_ru((tmax - tmin - 0.5f) * 0.03125f);
    nc = max(0, min(nc, 8));
    const int nfull = nc - 1;                 // chunks guaranteed fully live

    const float t0 = tmin + ((float)lane + 0.5f);

    float acc = 0.0f;
    int j = 0;
    for (; j + 1 < nfull; j += 2) {
        float sa = drr_sample_u(P, t0 + (float)(j * 32),      d0, d1, d2, s0, s1, s2);
        float sb = drr_sample_u(P, t0 + (float)(j * 32 + 32), d0, d1, d2, s0, s1, s2);
        acc += sa + sb;
    }
    if (j < nfull) {
        acc += drr_sample_u(P, t0 + (float)(j * 32), d0, d1, d2, s0, s1, s2);
        j++;
    }
    if (j < nc) {
        acc += drr_sample_m(P, t0 + (float)(j * 32), tmax, d0, d1, d2, s0, s1, s2);
    }

    #pragma unroll
    for (int off = 16; off > 0; off >>= 1)
        acc += __shfl_xor_sync(0xFFFFFFFFu, acc, off);

    if (lane == 0)
        out[ray] = acc * 0.1f;
}

extern "C" void kernel_launch(void* const* d_in, const int* in_sizes, int n_in,
                              void* d_out, int out_size)
{
    const float* vol    = (const float*)d_in[0];
    const float* params = (const float*)d_in[1];
    float* out = (float*)d_out;

    drr_border_kernel<<<(4 * PX * PY + 255) / 256, 256>>>();
    drr_pack_kernel<<<(4 * 128 * 128 * 16) / 256, 256>>>(vol);
    drr_setup_kernel<<<N_RAYS / 128, 128>>>(params);
    drr_march_kernel<<<N_RAYS / WARPS_PER_BLOCK, WARPS_PER_BLOCK * 32>>>(out);
}

// round 11
// speedup vs baseline: 1.0894x; 1.0894x over previous
#include <cuda_runtime.h>
#include <cuda_fp16.h>
#include <math.h>

#define N_RAYS (4*128*128)
#define WARPS_PER_BLOCK 8

// padded packed volume: P2(b, xp, yp, zp) = half2( vpad(x,y,z), vpad(x,y+1,z) )
// xp = x+1 (x in [-1,129]), yp = y+1 (y in [-1,128]), zp = z+4 (z in [-4,131])
#define PZ 136
#define PY 130
#define PX 131
#define SX (PY*PZ)             // 17680
#define PBATCH (PX*SX)         // 2316080
#define ROFF (SX + PZ + 4)     // 17820

__device__ float4   g_ray[N_RAYS * 2];
__device__ unsigned g_P2[4 * PBATCH];      // 37 MB

// ---------------- setup: per-ray geometry ----------------
__global__ void __launch_bounds__(128) drr_setup_kernel(
    const float* __restrict__ params)   // (4,6)
{
    const int ray = blockIdx.x * 128 + threadIdx.x;
    const int iv = ray & 127;
    const int iu = (ray >> 7) & 127;
    const int b  = ray >> 14;

    const float* p = params + b * 6;
    float sx, cx, sy, cy, sz, cz;
    __sincosf(p[0], &sx, &cx);
    __sincosf(p[1], &sy, &cy);
    __sincosf(p[2], &sz, &cz);

    float T00 = cy*cz,  T01 = cx*sz + sx*sy*cz,  T02 = sx*sz - cx*sy*cz;
    float T10 = -cy*sz, T11 = cx*cz - sx*sy*sz,  T12 = sx*cz + cx*sy*sz;
    float T20 = sy,     T21 = -sx*cy,            T22 = cx*cy;

    float tv0 = -p[3], tv1 = -p[4], tv2 = 1000.0f - p[5];
    float s0 = 64.0f - (T00*tv0 + T01*tv1 + T02*tv2);
    float s1 = 64.0f - (T10*tv0 + T11*tv1 + T12*tv2);
    float s2 = 64.0f - (T20*tv0 + T21*tv1 + T22*tv2);

    float qx = ((float)iu + 0.5f) * 0.001f - 0.064f;
    float qy = ((float)iv + 0.5f) * 0.001f - 0.064f;

    float d0 = T00*qx + T01*qy + T02;
    float d1 = T10*qx + T11*qy + T12;
    float d2 = T20*qx + T21*qy + T22;
    float nrm = sqrtf(d0*d0 + d1*d1 + d2*d2);
    d0 /= nrm; d1 /= nrm; d2 /= nrm;

    float sd0 = (fabsf(d0) < 1e-8f) ? 1e-8f : d0;
    float sd1 = (fabsf(d1) < 1e-8f) ? 1e-8f : d1;
    float sd2 = (fabsf(d2) < 1e-8f) ? 1e-8f : d2;
    float a0 = (0.0f - s0) / sd0, b0_ = (128.0f - s0) / sd0;
    float a1 = (0.0f - s1) / sd1, b1_ = (128.0f - s1) / sd1;
    float a2 = (0.0f - s2) / sd2, b2_ = (128.0f - s2) / sd2;
    float tmin = fmaxf(fmaxf(fminf(a0,b0_), fminf(a1,b1_)), fminf(a2,b2_));
    tmin = fmaxf(tmin, 0.0f);
    float tmax = fminf(fminf(fmaxf(a0,b0_), fmaxf(a1,b1_)), fmaxf(a2,b2_));

    g_ray[ray*2 + 0] = make_float4(s0, s1, s2, tmin);
    g_ray[ray*2 + 1] = make_float4(d0, d1, d2, tmax);
}

// ---------------- pack: interior rows (yp in [1,128]) ----------------
__global__ void __launch_bounds__(256) drr_pack_kernel(
    const float* __restrict__ vol)
{
    const int tid = blockIdx.x * 256 + threadIdx.x;   // 4*128*128*16
    const int zb = tid & 15;
    const int y  = (tid >> 4) & 127;
    const int x  = (tid >> 11) & 127;
    const int b  = tid >> 18;

    const size_t row = (((size_t)(b * 128 + x)) * 128 + y) * 128;
    const int z0 = zb * 8;

    float4 a0 = __ldg((const float4*)(vol + row + z0));
    float4 a1 = __ldg((const float4*)(vol + row + z0 + 4));
    float4 c0 = make_float4(0.f,0.f,0.f,0.f), c1 = c0;
    if (y < 127) {
        c0 = __ldg((const float4*)(vol + row + 128 + z0));
        c1 = __ldg((const float4*)(vol + row + 128 + z0 + 4));
    }

    __half2 h0 = __floats2half2_rn(a0.x, c0.x);
    __half2 h1 = __floats2half2_rn(a0.y, c0.y);
    __half2 h2 = __floats2half2_rn(a0.z, c0.z);
    __half2 h3 = __floats2half2_rn(a0.w, c0.w);
    __half2 h4 = __floats2half2_rn(a1.x, c1.x);
    __half2 h5 = __floats2half2_rn(a1.y, c1.y);
    __half2 h6 = __floats2half2_rn(a1.z, c1.z);
    __half2 h7 = __floats2half2_rn(a1.w, c1.w);

    uint4 o0, o1;
    o0.x = *reinterpret_cast<unsigned*>(&h0);
    o0.y = *reinterpret_cast<unsigned*>(&h1);
    o0.z = *reinterpret_cast<unsigned*>(&h2);
    o0.w = *reinterpret_cast<unsigned*>(&h3);
    o1.x = *reinterpret_cast<unsigned*>(&h4);
    o1.y = *reinterpret_cast<unsigned*>(&h5);
    o1.z = *reinterpret_cast<unsigned*>(&h6);
    o1.w = *reinterpret_cast<unsigned*>(&h7);

    size_t w = (size_t)b * PBATCH + (size_t)(x + 1) * SX + (size_t)(y + 1) * PZ + (z0 + 4);
    *reinterpret_cast<uint4*>(&g_P2[w])     = o0;
    *reinterpret_cast<uint4*>(&g_P2[w + 4]) = o1;
}

// ---------------- pack: borders + y0 plane (fused) ----------------
#define NB_BORDER (4 * PX * PY)            // zero rows / z-pads
#define NB_Y0     (4 * 128 * 16)           // y = -1 plane threads
__global__ void __launch_bounds__(256) drr_border_kernel(
    const float* __restrict__ vol)
{
    const int t = blockIdx.x * 256 + threadIdx.x;
    if (t < NB_BORDER) {
        const int yp = t % PY;
        const int r2 = t / PY;
        const int xp = r2 % PX;
        const int b  = r2 / PX;

        size_t base = (size_t)b * PBATCH + (size_t)xp * SX + (size_t)yp * PZ;
        uint4 z4 = make_uint4(0u, 0u, 0u, 0u);

        if (xp == 0 || xp == 129 || xp == 130 || yp == 129) {
            #pragma unroll
            for (int i = 0; i < PZ / 4; i++)
                *reinterpret_cast<uint4*>(&g_P2[base + i * 4]) = z4;
        } else {
            *reinterpret_cast<uint4*>(&g_P2[base])       = z4;   // z pads -4..-1
            *reinterpret_cast<uint4*>(&g_P2[base + 132]) = z4;   // z pads 128..131
        }
        return;
    }
    const int t2 = t - NB_BORDER;
    if (t2 >= NB_Y0) return;
    // yp = 0 plane (y = -1): pair = (0, v(x,0,z))
    const int zb = t2 & 15;
    const int x  = (t2 >> 4) & 127;
    const int b  = t2 >> 11;

    const size_t row = ((size_t)(b * 128 + x)) * 128 * 128;   // y = 0 row
    const int z0 = zb * 8;

    float4 a0 = __ldg((const float4*)(vol + row + z0));
    float4 a1 = __ldg((const float4*)(vol + row + z0 + 4));

    __half2 h0 = __floats2half2_rn(0.f, a0.x);
    __half2 h1 = __floats2half2_rn(0.f, a0.y);
    __half2 h2 = __floats2half2_rn(0.f, a0.z);
    __half2 h3 = __floats2half2_rn(0.f, a0.w);
    __half2 h4 = __floats2half2_rn(0.f, a1.x);
    __half2 h5 = __floats2half2_rn(0.f, a1.y);
    __half2 h6 = __floats2half2_rn(0.f, a1.z);
    __half2 h7 = __floats2half2_rn(0.f, a1.w);

    uint4 o0, o1;
    o0.x = *reinterpret_cast<unsigned*>(&h0);
    o0.y = *reinterpret_cast<unsigned*>(&h1);
    o0.z = *reinterpret_cast<unsigned*>(&h2);
    o0.w = *reinterpret_cast<unsigned*>(&h3);
    o1.x = *reinterpret_cast<unsigned*>(&h4);
    o1.y = *reinterpret_cast<unsigned*>(&h5);
    o1.z = *reinterpret_cast<unsigned*>(&h6);
    o1.w = *reinterpret_cast<unsigned*>(&h7);

    size_t w = (size_t)b * PBATCH + (size_t)(x + 1) * SX + (z0 + 4);
    *reinterpret_cast<uint4*>(&g_P2[w])     = o0;
    *reinterpret_cast<uint4*>(&g_P2[w + 4]) = o1;
}

// ---------------- march ----------------
__device__ __forceinline__ float drr_lerp(
    const unsigned* __restrict__ P,
    float px, float py, float pz)
{
    float fx = floorf(px), fy = floorf(py), fz = floorf(pz);
    float rx = px - fx, ry = py - fy, rz = pz - fz;

    int r = (int)fmaf(fx, (float)SX, fmaf(fy, (float)PZ, fz + (float)ROFF));

    unsigned u00 = __ldg(P + r);            // (x  ): (v(y,z), v(y+1,z))
    unsigned u01 = __ldg(P + r + 1);        // (x  ): z+1 pair  -> same 128B line
    unsigned u10 = __ldg(P + r + SX);       // (x+1)
    unsigned u11 = __ldg(P + r + SX + 1);

    float2 f00 = __half22float2(*reinterpret_cast<__half2*>(&u00));
    float2 f01 = __half22float2(*reinterpret_cast<__half2*>(&u01));
    float2 f10 = __half22float2(*reinterpret_cast<__half2*>(&u10));
    float2 f11 = __half22float2(*reinterpret_cast<__half2*>(&u11));

    float z0a = fmaf(rz, f01.x - f00.x, f00.x);
    float z0b = fmaf(rz, f01.y - f00.y, f00.y);
    float z1a = fmaf(rz, f11.x - f10.x, f10.x);
    float z1b = fmaf(rz, f11.y - f10.y, f10.y);
    float ly0 = fmaf(ry, z0b - z0a, z0a);
    float ly1 = fmaf(ry, z1b - z1a, z1a);
    return fmaf(rx, ly1 - ly0, ly0);
}

// unmasked: valid only when every lane in the chunk is live (j <= nc-2)
__device__ __forceinline__ float drr_sample_u(
    const unsigned* __restrict__ P, float tk,
    float d0, float d1, float d2, float s0, float s1, float s2)
{
    return drr_lerp(P, fmaf(tk, d0, s0), fmaf(tk, d1, s1), fmaf(tk, d2, s2));
}

// masked (final chunk)
__device__ __forceinline__ float drr_sample_m(
    const unsigned* __restrict__ P, float tk, float tmax,
    float d0, float d1, float d2, float s0, float s1, float s2)
{
    float tc = fminf(tk, tmax);
    float s = drr_lerp(P, fmaf(tc, d0, s0), fmaf(tc, d1, s1), fmaf(tc, d2, s2));
    return (tk < tmax) ? s : 0.0f;
}

__global__ void __launch_bounds__(WARPS_PER_BLOCK * 32, 8) drr_march_kernel(
    float* __restrict__ out)
{
    const int lane    = threadIdx.x & 31;
    const int warp_id = threadIdx.x >> 5;
    const int ray     = blockIdx.x * WARPS_PER_BLOCK + warp_id;
    const int b       = ray >> 14;

    const float4 A = __ldg(&g_ray[ray*2 + 0]);
    const float4 B = __ldg(&g_ray[ray*2 + 1]);
    const float s0 = A.x, s1 = A.y, s2 = A.z, tmin = A.w;
    const float d0 = B.x, d1 = B.y, d2 = B.z, tmax = B.w;

    const unsigned* __restrict__ P = g_P2 + (size_t)b * PBATCH;

    // nc = ceil((tmax - tmin - 0.5)/32); chunks j <= nc-2 are provably fully live
    int nc = __float2int_ru((tmax - tmin - 0.5f) * 0.03125f);
    nc = max(0, min(nc, 8));
    const int nfull = nc - 1;

    const float t0 = tmin + ((float)lane + 0.5f);

    float acc = 0.0f;
    int j = 0;
    for (; j + 1 < nfull; j += 2) {
        float sa = drr_sample_u(P, t0 + (float)(j * 32),      d0, d1, d2, s0, s1, s2);
        float sb = drr_sample_u(P, t0 + (float)(j * 32 + 32), d0, d1, d2, s0, s1, s2);
        acc += sa + sb;
    }
    if (j < nfull) {
        acc += drr_sample_u(P, t0 + (float)(j * 32), d0, d1, d2, s0, s1, s2);
        j++;
    }
    if (j < nc) {
        acc += drr_sample_m(P, t0 + (float)(j * 32), tmax, d0, d1, d2, s0, s1, s2);
    }

    #pragma unroll
    for (int off = 16; off > 0; off >>= 1)
        acc += __shfl_xor_sync(0xFFFFFFFFu, acc, off);

    if (lane == 0)
        out[ray] = acc * 0.1f;
}

extern "C" void kernel_launch(void* const* d_in, const int* in_sizes, int n_in,
                              void* d_out, int out_size)
{
    const float* vol    = (const float*)d_in[0];
    const float* params = (const float*)d_in[1];
    float* out = (float*)d_out;

    drr_border_kernel<<<(NB_BORDER + NB_Y0 + 255) / 256, 256>>>(vol);
    drr_pack_kernel<<<(4 * 128 * 128 * 16) / 256, 256>>>(vol);
    drr_setup_kernel<<<N_RAYS / 128, 128>>>(params);
    drr_march_kernel<<<N_RAYS / WARPS_PER_BLOCK, WARPS_PER_BLOCK * 32>>>(out);
}